// round 14
// baseline (speedup 1.0000x reference)
#include <cuda_runtime.h>
#include <cuda_fp16.h>
#include <cstdint>

#define NTOK_MAX (8 * 4096)
#define IN_F 1024
#define CUT1 5000
#define CUT2 20000

// B' scratch: last 384 out rows (B0 fp16 1024x512 = 1MB, B1 1024x256 = .5MB).
// A is gathered+converted ONCE per token into persistent CTA smem (no scratch).
#define CUTROW2 (NTOK_MAX - 384)

__device__ int g_cnt4[4];   // {t0_lo, t0_hi, t1_lo, t1_hi}
__device__ int g_l0[NTOK_MAX];
__device__ int g_l1[NTOK_MAX];
__device__ int g_h0[NTOK_MAX];
__device__ int g_h1[NTOK_MAX];

// ---------------------------------------------------------------------------
__global__ void init_k() {
    if (threadIdx.x < 4) g_cnt4[threadIdx.x] = 0;
}

__global__ void classify4_k(const int* __restrict__ tokens, int n) {
    int i = blockIdx.x * blockDim.x + threadIdx.x;
    int t = (i < n) ? tokens[i] : -1;
    int c = (t >= CUT2) ? 1 : ((t >= CUT1) ? 0 : -1);
    int hh = (i >= CUTROW2) ? 1 : 0;
    int lane = threadIdx.x & 31;
#pragma unroll
    for (int cc = 0; cc < 2; ++cc) {
#pragma unroll
        for (int h2 = 0; h2 < 2; ++h2) {
            unsigned m = __ballot_sync(0xffffffffu, c == cc && hh == h2);
            if (c == cc && hh == h2) {
                int leader = __ffs(m) - 1;
                int base = 0;
                if (lane == leader) base = atomicAdd(&g_cnt4[cc * 2 + h2], __popc(m));
                base = __shfl_sync(m, base, leader);
                int slot = base + __popc(m & ((1u << lane) - 1u));
                int* lst = h2 ? (cc ? g_h1 : g_h0) : (cc ? g_l1 : g_l0);
                lst[slot] = i;
            }
        }
    }
}

__global__ void head_lo_k(const int* __restrict__ tokens,
                          const float* __restrict__ head_emb,
                          float* __restrict__ out) {
    int p = blockIdx.x;                      // < CUTROW2 by grid
    int t = __ldg(&tokens[p]);
    if (t >= CUT1) return;
    const float4* src = (const float4*)(head_emb + (size_t)t * IN_F);
    float4* dst = (float4*)(out + (size_t)p * IN_F);
    dst[threadIdx.x]       = src[threadIdx.x];
    dst[threadIdx.x + 128] = src[threadIdx.x + 128];
}

__global__ void head_hi_k(const int* __restrict__ tokens,
                          const float* __restrict__ head_emb,
                          float* __restrict__ out, int n) {
    int p = CUTROW2 + blockIdx.x;
    if (p >= n) return;
    int t = __ldg(&tokens[p]);
    if (t >= CUT1) return;
    const float4* src = (const float4*)(head_emb + (size_t)t * IN_F);
    float4* dst = (float4*)(out + (size_t)p * IN_F);
    dst[threadIdx.x]       = src[threadIdx.x];
    dst[threadIdx.x + 128] = src[threadIdx.x + 128];
}

// ---------------------------------------------------------------------------
__device__ __forceinline__ uint32_t cvt2(float f0, float f1) {
    uint32_t r;
    asm("cvt.rn.f16x2.f32 %0, %1, %2;" : "=r"(r) : "f"(f1), "f"(f0));
    return r;
}

// Convert both weight matrices into fp16 B' scratch (tail 384 rows of out).
__global__ void packB_k(const float* __restrict__ w0,
                        const float* __restrict__ w1,
                        float* __restrict__ out) {
    __half* B0 = (__half*)(out + (size_t)CUTROW2 * IN_F);
    __half* B1 = B0 + (size_t)1024 * 512;
    int K, r, j;
    const float* w;
    __half* Bp;
    if (blockIdx.x < 128) {
        K = 512; w = w0; Bp = B0;
        r = blockIdx.x * 8 + threadIdx.x / 32;
        j = (threadIdx.x % 32) * 16;
    } else {
        K = 256; w = w1; Bp = B1;
        r = (blockIdx.x - 128) * 16 + threadIdx.x / 16;
        j = (threadIdx.x % 16) * 16;
    }
    const float4* src = (const float4*)(w + (size_t)r * K + j);
    float4 v0 = src[0], v1 = src[1], v2 = src[2], v3 = src[3];
    uint4 o0 = make_uint4(cvt2(v0.x, v0.y), cvt2(v0.z, v0.w),
                          cvt2(v1.x, v1.y), cvt2(v1.z, v1.w));
    uint4 o1 = make_uint4(cvt2(v2.x, v2.y), cvt2(v2.z, v2.w),
                          cvt2(v3.x, v3.y), cvt2(v3.z, v3.w));
    __half* dst = Bp + (size_t)r * K + j;
    *(uint4*)dst = o0;
    *(uint4*)(dst + 8) = o1;
}

// ---------------------------------------------------------------------------
__device__ __forceinline__ void ldsm_x4(uint32_t& r0, uint32_t& r1,
                                        uint32_t& r2, uint32_t& r3,
                                        const void* smem_ptr) {
    uint32_t addr = (uint32_t)__cvta_generic_to_shared(smem_ptr);
    asm volatile("ldmatrix.sync.aligned.m8n8.x4.shared.b16 {%0,%1,%2,%3}, [%4];"
                 : "=r"(r0), "=r"(r1), "=r"(r2), "=r"(r3) : "r"(addr));
}

__device__ __forceinline__ void mma16816(float* c, const uint32_t* a,
                                         uint32_t b0, uint32_t b1) {
    asm volatile(
        "mma.sync.aligned.m16n8k16.row.col.f32.f16.f16.f32 "
        "{%0,%1,%2,%3}, {%4,%5,%6,%7}, {%8,%9}, {%0,%1,%2,%3};"
        : "+f"(c[0]), "+f"(c[1]), "+f"(c[2]), "+f"(c[3])
        : "r"(a[0]), "r"(a[1]), "r"(a[2]), "r"(a[3]), "r"(b0), "r"(b1));
}

__device__ __forceinline__ void cp16(void* dst_smem, const void* src) {
    uint32_t d = (uint32_t)__cvta_generic_to_shared(dst_smem);
    asm volatile("cp.async.cg.shared.global [%0], [%1], 16;\n" :: "r"(d), "l"(src));
}

// ---------------------------------------------------------------------------
// Persistent-A dense GEMM. CTA = 128 lo-list rows x full N=1024.
// Phase 1: gather + fp32->fp16 convert A ONCE into persistent smem.
// Phase 2: 8 N-slices of 128, B' (packed fp16) streamed via 2-stage cp.async,
// 8 warps (2M x 4N, warp tile 64x32). Per-slice epilogue scatter-stores.
template <int K, int C, int MINB>
__global__ void __launch_bounds__(256, MINB)
dense3_k(const float* __restrict__ emb,
         const int* __restrict__ tokens,
         const __half* __restrict__ Bp,
         float* __restrict__ out) {
    constexpr int LDA = K + 8;             // halves; rows span all 32 banks
    constexpr int LDB = 72;
    constexpr int NCK = K / 64;            // K chunks of 64 halves
    constexpr int G = 8 * NCK;             // slices x chunks
    constexpr int LOW = C ? CUT2 : CUT1;
    extern __shared__ __half dsm[];
    __half* Asm = dsm;                     // [128][LDA]
    __half* Bsm = dsm + 128 * LDA;         // [2][128][LDB]
    __shared__ int sPos[128];

    const int count = g_cnt4[C * 2];
    const int rowBase = blockIdx.x * 128;
    if (rowBase >= count) return;
    const int rem = min(128, count - rowBase);
    const int tid = threadIdx.x;
    const int lane = tid & 31;
    const int wid = tid >> 5;

    if (tid < 128) sPos[tid] = (C ? g_l1 : g_l0)[rowBase + min(tid, rem - 1)];
    __syncthreads();

    // ---- Phase 1: gather + convert A (2 threads per row, K/2 floats each)
    {
        const int row = tid >> 1;
        const int h = tid & 1;
        const int tok = __ldg(&tokens[sPos[row]]) - LOW;
        const float4* src = (const float4*)(emb + (size_t)tok * K + h * (K / 2));
        __half* drow = Asm + row * LDA + h * (K / 2);
#pragma unroll
        for (int q = 0; q < K / 16; q++) {
            float4 a = src[q * 2], b = src[q * 2 + 1];
            uint4 o = make_uint4(cvt2(a.x, a.y), cvt2(a.z, a.w),
                                 cvt2(b.x, b.y), cvt2(b.z, b.w));
            *(uint4*)(drow + q * 8) = o;
        }
    }

    // ---- Phase 2: stream B' slices
    const int brow = tid >> 1;
#define BISSUE(g)                                                         \
    do {                                                                  \
        int s0_ = (g) / NCK, kc_ = (g) % NCK, stg_ = (g) & 1;             \
        const __half* bsrc = Bp + (size_t)(s0_ * 128 + brow) * K          \
                             + kc_ * 64;                                  \
        __half* bdst = Bsm + stg_ * (128 * LDB) + brow * LDB;             \
        _Pragma("unroll")                                                 \
        for (int p_ = 0; p_ < 4; p_++) {                                  \
            int col = ((tid & 1) + p_ * 2) * 8;                           \
            cp16(bdst + col, bsrc + col);                                 \
        }                                                                 \
    } while (0)

    BISSUE(0);
    asm volatile("cp.async.commit_group;\n");

    const int wm = (wid & 1) * 64;
    const int wn = (wid >> 1) * 32;
    float c[4][4][4];
#pragma unroll
    for (int i = 0; i < 4; i++)
#pragma unroll
        for (int j = 0; j < 4; j++)
#pragma unroll
            for (int q = 0; q < 4; q++) c[i][j][q] = 0.f;

    const int aLdRow = lane & 15;
    const int aLdCol = (lane >> 4) * 8;
    const int bLdRow = ((lane >> 4) << 3) + (lane & 7);
    const int bLdCol = lane & 8;

#pragma unroll 1
    for (int g = 0; g < G; g++) {
        asm volatile("cp.async.wait_group 0;\n");
        __syncthreads();                   // B stage ready; A ready (1st iter)
        if (g + 1 < G) {
            BISSUE(g + 1);                 // other buffer; overlaps MMA below
            asm volatile("cp.async.commit_group;\n");
        }
        const int s0 = g / NCK, kc = g % NCK, stg = g & 1;
        const __half* bb = Bsm + stg * (128 * LDB);
#pragma unroll
        for (int kf = 0; kf < 4; kf++) {
            uint32_t AF[4][4], BF[2][4];
#pragma unroll
            for (int mf = 0; mf < 4; mf++)
                ldsm_x4(AF[mf][0], AF[mf][1], AF[mf][2], AF[mf][3],
                        &Asm[(wm + mf * 16 + aLdRow) * LDA
                             + kc * 64 + kf * 16 + aLdCol]);
#pragma unroll
            for (int gg = 0; gg < 2; gg++)
                ldsm_x4(BF[gg][0], BF[gg][1], BF[gg][2], BF[gg][3],
                        bb + (wn + gg * 16 + bLdRow) * LDB + kf * 16 + bLdCol);
#pragma unroll
            for (int mf = 0; mf < 4; mf++)
#pragma unroll
                for (int nf = 0; nf < 4; nf++)
                    mma16816(c[mf][nf], AF[mf],
                             BF[nf >> 1][(nf & 1) * 2], BF[nf >> 1][(nf & 1) * 2 + 1]);
        }

        if (kc == NCK - 1) {               // slice epilogue
            int n0 = s0 * 128;
#pragma unroll
            for (int mf = 0; mf < 4; mf++) {
#pragma unroll
                for (int nf = 0; nf < 4; nf++) {
                    int r0 = wm + mf * 16 + (lane >> 2);
                    int col = n0 + wn + nf * 8 + 2 * (lane & 3);
                    if (r0 < rem)
                        *(float2*)(out + (size_t)sPos[r0] * IN_F + col) =
                            make_float2(c[mf][nf][0], c[mf][nf][1]);
                    if (r0 + 8 < rem)
                        *(float2*)(out + (size_t)sPos[r0 + 8] * IN_F + col) =
                            make_float2(c[mf][nf][2], c[mf][nf][3]);
#pragma unroll
                    for (int q = 0; q < 4; q++) c[mf][nf][q] = 0.f;
                }
            }
        }
    }
#undef BISSUE
}

// ---------------------------------------------------------------------------
// Fused gather+convert fp16 GEMM for the 384 scratch rows (R9/R10-proven).
template <int K, int LOW, int C>
__global__ void __launch_bounds__(256, 2)
fused_hi_k(const float* __restrict__ emb,
           const float* __restrict__ w,
           const int* __restrict__ tokens,
           float* __restrict__ out) {
    constexpr int TM = 128, TN = 128, LD = 40;
    constexpr int NC = K / 32;
    __shared__ __align__(16) __half sA[2][TM][LD];
    __shared__ __align__(16) __half sB[2][TN][LD];
    __shared__ int sPos[TM];

    const int count = g_cnt4[C * 2 + 1];
    const int rowBase = blockIdx.x * TM;
    if (rowBase >= count) return;
    const int rem = min(TM, count - rowBase);
    const int n0 = blockIdx.y * TN;
    const int tid = threadIdx.x;
    const int lane = tid & 31;
    const int wid = tid >> 5;

    if (tid < TM) sPos[tid] = (C ? g_h1 : g_h0)[rowBase + min(tid, rem - 1)];
    __syncthreads();

    const int ar = tid >> 1;
    const int aseg = (tid & 1) * 16;
    const float* aPtr = emb + (size_t)(__ldg(&tokens[sPos[ar]]) - LOW) * K + aseg;
    const float* bPtr = w + (size_t)(n0 + ar) * K + aseg;

    float ra[16], rb[16];
#define LOADREGS(kc)                                              \
    do {                                                          \
        const float* ap_ = aPtr + (kc) * 32;                      \
        const float* bp_ = bPtr + (kc) * 32;                      \
        _Pragma("unroll")                                         \
        for (int q_ = 0; q_ < 4; q_++) {                          \
            float4 va_ = *(const float4*)(ap_ + q_ * 4);          \
            float4 vb_ = *(const float4*)(bp_ + q_ * 4);          \
            ra[q_*4+0]=va_.x; ra[q_*4+1]=va_.y;                   \
            ra[q_*4+2]=va_.z; ra[q_*4+3]=va_.w;                   \
            rb[q_*4+0]=vb_.x; rb[q_*4+1]=vb_.y;                   \
            rb[q_*4+2]=vb_.z; rb[q_*4+3]=vb_.w;                   \
        }                                                         \
    } while (0)

#define CVTSTS(buf)                                                            \
    do {                                                                       \
        *(uint4*)&sA[buf][ar][aseg] =                                          \
            make_uint4(cvt2(ra[0], ra[1]), cvt2(ra[2], ra[3]),                 \
                       cvt2(ra[4], ra[5]), cvt2(ra[6], ra[7]));                \
        *(uint4*)&sA[buf][ar][aseg + 8] =                                      \
            make_uint4(cvt2(ra[8], ra[9]),  cvt2(ra[10], ra[11]),              \
                       cvt2(ra[12], ra[13]), cvt2(ra[14], ra[15]));            \
        *(uint4*)&sB[buf][ar][aseg] =                                          \
            make_uint4(cvt2(rb[0], rb[1]), cvt2(rb[2], rb[3]),                 \
                       cvt2(rb[4], rb[5]), cvt2(rb[6], rb[7]));                \
        *(uint4*)&sB[buf][ar][aseg + 8] =                                      \
            make_uint4(cvt2(rb[8], rb[9]),  cvt2(rb[10], rb[11]),              \
                       cvt2(rb[12], rb[13]), cvt2(rb[14], rb[15]));            \
    } while (0)

    const int wm = (wid & 1) * 64;
    const int wn = (wid >> 1) * 32;
    float c[4][4][4];
#pragma unroll
    for (int i = 0; i < 4; i++)
#pragma unroll
        for (int j = 0; j < 4; j++)
#pragma unroll
            for (int q = 0; q < 4; q++) c[i][j][q] = 0.f;

    const int aLdRow = lane & 15;
    const int aLdCol = (lane >> 4) * 8;
    const int bLdRow = ((lane >> 4) << 3) + (lane & 7);
    const int bLdCol = lane & 8;

#define MMA_STAGE(buf)                                                        \
    do {                                                                      \
        _Pragma("unroll")                                                     \
        for (int kf = 0; kf < 2; kf++) {                                      \
            uint32_t AF[4][4], BF[2][4];                                      \
            _Pragma("unroll")                                                 \
            for (int mf = 0; mf < 4; mf++)                                    \
                ldsm_x4(AF[mf][0], AF[mf][1], AF[mf][2], AF[mf][3],           \
                        &sA[buf][wm + mf*16 + aLdRow][kf*16 + aLdCol]);       \
            _Pragma("unroll")                                                 \
            for (int g = 0; g < 2; g++)                                       \
                ldsm_x4(BF[g][0], BF[g][1], BF[g][2], BF[g][3],               \
                        &sB[buf][wn + g*16 + bLdRow][kf*16 + bLdCol]);        \
            _Pragma("unroll")                                                 \
            for (int mf = 0; mf < 4; mf++)                                    \
                _Pragma("unroll")                                             \
                for (int nf = 0; nf < 4; nf++)                                \
                    mma16816(c[mf][nf], AF[mf],                               \
                             BF[nf >> 1][(nf & 1) * 2],                       \
                             BF[nf >> 1][(nf & 1) * 2 + 1]);                  \
        }                                                                     \
    } while (0)

    LOADREGS(0);
    CVTSTS(0);

    int b = 0;
#pragma unroll 1
    for (int kc = 0; kc < NC; kc++) {
        if (kc + 1 < NC) LOADREGS(kc + 1);
        __syncthreads();
        MMA_STAGE(b);
        if (kc + 1 < NC) CVTSTS(b ^ 1);
        b ^= 1;
    }
#undef LOADREGS
#undef CVTSTS
#undef MMA_STAGE

#pragma unroll
    for (int mf = 0; mf < 4; mf++) {
#pragma unroll
        for (int nf = 0; nf < 4; nf++) {
            int r0 = wm + mf * 16 + (lane >> 2);
            int col = n0 + wn + nf * 8 + 2 * (lane & 3);
            if (r0 < rem)
                *(float2*)(out + (size_t)sPos[r0] * IN_F + col) =
                    make_float2(c[mf][nf][0], c[mf][nf][1]);
            if (r0 + 8 < rem)
                *(float2*)(out + (size_t)sPos[r0 + 8] * IN_F + col) =
                    make_float2(c[mf][nf][2], c[mf][nf][3]);
        }
    }
}

// ---------------------------------------------------------------------------
extern "C" void kernel_launch(void* const* d_in, const int* in_sizes, int n_in,
                              void* d_out, int out_size) {
    const int*   tokens   = (const int*)d_in[0];
    const float* head_emb = (const float*)d_in[1];
    const float* t0e      = (const float*)d_in[2];
    const float* t0w      = (const float*)d_in[3];
    const float* t1e      = (const float*)d_in[4];
    const float* t1w      = (const float*)d_in[5];
    float* out = (float*)d_out;
    int n = in_sizes[0];
    if (n > NTOK_MAX) n = NTOK_MAX;

    const __half* B0 = (const __half*)(out + (size_t)CUTROW2 * IN_F);
    const __half* B1 = B0 + (size_t)1024 * 512;

    const int smem0 = (128 * 520 + 2 * 128 * 72) * (int)sizeof(__half); // 169984
    const int smem1 = (128 * 264 + 2 * 128 * 72) * (int)sizeof(__half); // 104448
    cudaFuncSetAttribute(dense3_k<512, 0, 1>,
                         cudaFuncAttributeMaxDynamicSharedMemorySize, smem0);
    cudaFuncSetAttribute(dense3_k<256, 1, 2>,
                         cudaFuncAttributeMaxDynamicSharedMemorySize, smem1);

    init_k<<<1, 32>>>();
    classify4_k<<<(n + 255) / 256, 256>>>(tokens, n);
    packB_k<<<192, 256>>>(t0w, t1w, out);

    // dense: lo rows (pos < CUTROW2); A fused once per token, B' from scratch
    dense3_k<512, 0, 1><<<(n + 127) / 128, 256, smem0>>>(t0e, tokens, B0, out);
    dense3_k<256, 1, 2><<<(n + 127) / 128, 256, smem1>>>(t1e, tokens, B1, out);

    head_lo_k<<<CUTROW2, 128>>>(tokens, head_emb, out);
    // after dense consumed B' scratch: write the 384 scratch-region rows
    head_hi_k<<<NTOK_MAX - CUTROW2, 128>>>(tokens, head_emb, out, n);
    fused_hi_k<512, CUT1, 0><<<dim3(3, IN_F / 128), 256>>>(t0e, t0w, tokens, out);
    fused_hi_k<256, CUT2, 1><<<dim3(3, IN_F / 128), 256>>>(t1e, t1w, tokens, out);
}